// round 16
// baseline (speedup 1.0000x reference)
#include <cuda_runtime.h>
#include <cuda_bf16.h>

#define NQ      14
#define NSTATES (1 << NQ)          // 16384
#define THREADS 256
#define ITERS   (NSTATES / (THREADS * 4))   // 16

// FINAL (held) — converged at the B300 LTS fabric roofline (~6.7-6.8 TB/s).
// 512 MiB of fp32 amplitudes read exactly once; floor = traffic / chip cap
// ~= 79-81 us, achieved. Sixteen samples (7 structural variants + repeats of
// this binary) span 79.6-81.3 us; this binary itself sampled both extremes ->
// spread is chip-cap run-to-run variation, not kernel structure. Invariant to:
// block size (256/512), burst width (16/32B), cache policy (default/__ldcs),
// epilogue shape, occupancy point (61-72%), grid/wave structure (4096 CTAs vs
// persistent 888). Non-levers per measured HW model: TMA (same LTS path),
// HBM striding (binds upstream), L2 reuse (once-touched stream >> L2).
// fma 14% / issue 20% -> cleanly memory-bound at the fabric ceiling.
//
// One block per batch row. Each thread streams 16 float4 pairs (fully
// unrolled). The Pauli-Z sign structure factors over the bit-fields of the
// element index n = it*1024 + tid*4 + j:
//   bits 0..1  (j)    -> D0 (n-bit 0), D1 (n-bit 1): fixed intra-float4 signs
//   bits 2..9  (tid)  -> sign constant per thread: +-S applied once at the end
//   bits 10..13(it)   -> compile-time +- under full unroll (A10..A13)
// reducing per-element work to ~11 FP ops for all 14 qubits at once.
__global__ __launch_bounds__(THREADS)
void measurement_kernel(const float* __restrict__ sr,
                        const float* __restrict__ si,
                        float* __restrict__ out)
{
    const int row = blockIdx.x;
    const int tid = threadIdx.x;

    const float4* __restrict__ sr4 =
        reinterpret_cast<const float4*>(sr + (size_t)row * NSTATES);
    const float4* __restrict__ si4 =
        reinterpret_cast<const float4*>(si + (size_t)row * NSTATES);

    float D0 = 0.f, D1 = 0.f, S = 0.f;
    float A10 = 0.f, A11 = 0.f, A12 = 0.f, A13 = 0.f;

#pragma unroll
    for (int it = 0; it < ITERS; ++it) {
        const int idx = it * THREADS + tid;
        const float4 a = sr4[idx];
        const float4 b = si4[idx];

        const float p0 = a.x * a.x + b.x * b.x;
        const float p1 = a.y * a.y + b.y * b.y;
        const float p2 = a.z * a.z + b.z * b.z;
        const float p3 = a.w * a.w + b.w * b.w;

        const float s01 = p0 + p1;
        const float s23 = p2 + p3;
        const float s   = s01 + s23;

        D0 += (p0 - p1) + (p2 - p3);   // n-bit 0
        D1 += s01 - s23;               // n-bit 1
        S  += s;                       // n-bits 2..9 (per-thread sign below)

        // n-bits 10..13: 'it' is a compile-time constant under full unroll
        A10 += (it & 1) ? -s : s;
        A11 += (it & 2) ? -s : s;
        A12 += (it & 4) ? -s : s;
        A13 += (it & 8) ? -s : s;
    }

    // Expand to the 14 per-qubit partial sums.
    // Qubit q corresponds to n-bit b = 13 - q (qubit 0 is the MSB).
    float v[NQ];
    v[0] = A13;  // b=13
    v[1] = A12;  // b=12
    v[2] = A11;  // b=11
    v[3] = A10;  // b=10
#pragma unroll
    for (int q = 4; q <= 11; ++q) {
        const int b   = 13 - q;               // 9..2
        const int bit = (tid >> (b - 2)) & 1; // n-bit b == tid bit (b-2)
        v[q] = bit ? -S : S;
    }
    v[12] = D1;  // b=1
    v[13] = D0;  // b=0

    // Warp butterfly reduction of all 14 values.
#pragma unroll
    for (int q = 0; q < NQ; ++q) {
#pragma unroll
        for (int off = 16; off > 0; off >>= 1)
            v[q] += __shfl_xor_sync(0xffffffffu, v[q], off);
    }

    __shared__ float red[THREADS / 32][NQ];
    const int warp = tid >> 5;
    const int lane = tid & 31;
    if (lane == 0) {
#pragma unroll
        for (int q = 0; q < NQ; ++q) red[warp][q] = v[q];
    }
    __syncthreads();

    if (tid < NQ) {
        float r = 0.f;
#pragma unroll
        for (int w = 0; w < THREADS / 32; ++w) r += red[w][tid];
        out[(size_t)row * NQ + tid] = r;
    }
}

extern "C" void kernel_launch(void* const* d_in, const int* in_sizes, int n_in,
                              void* d_out, int out_size)
{
    const float* sr = (const float*)d_in[0];  // state_real [4096, 16384]
    const float* si = (const float*)d_in[1];  // state_imag [4096, 16384]
    float* out = (float*)d_out;               // [4096, 14]

    const int batch = in_sizes[0] / NSTATES;  // 4096
    measurement_kernel<<<batch, THREADS>>>(sr, si, out);
}

// round 17
// speedup vs baseline: 1.0140x; 1.0140x over previous
#include <cuda_runtime.h>
#include <cuda_bf16.h>

#define NQ      14
#define NSTATES (1 << NQ)          // 16384
#define THREADS 256
#define ITERS   (NSTATES / (THREADS * 4))   // 16

// FINAL (held) — converged at the B300 LTS fabric roofline (~6.7-6.8 TB/s).
// 512 MiB of fp32 amplitudes read exactly once; floor = traffic / chip cap
// ~= 79-81 us, achieved. Seventeen samples (7 structural variants + repeats
// of this binary) span 79.6-81.3 us; this binary itself sampled both extremes
// -> spread is chip-cap run-to-run variation, not kernel structure. Invariant
// to: block size (256/512), burst width (16/32B), cache policy
// (default/__ldcs), epilogue shape, occupancy point (61-72%), grid/wave
// structure (4096 CTAs vs persistent 888). Non-levers per measured HW model:
// TMA (same LTS path), HBM striding (binds upstream), L2 reuse (once-touched
// stream >> L2). fma 14% / issue 20% -> cleanly memory-bound at the ceiling.
//
// One block per batch row. Each thread streams 16 float4 pairs (fully
// unrolled). The Pauli-Z sign structure factors over the bit-fields of the
// element index n = it*1024 + tid*4 + j:
//   bits 0..1  (j)    -> D0 (n-bit 0), D1 (n-bit 1): fixed intra-float4 signs
//   bits 2..9  (tid)  -> sign constant per thread: +-S applied once at the end
//   bits 10..13(it)   -> compile-time +- under full unroll (A10..A13)
// reducing per-element work to ~11 FP ops for all 14 qubits at once.
__global__ __launch_bounds__(THREADS)
void measurement_kernel(const float* __restrict__ sr,
                        const float* __restrict__ si,
                        float* __restrict__ out)
{
    const int row = blockIdx.x;
    const int tid = threadIdx.x;

    const float4* __restrict__ sr4 =
        reinterpret_cast<const float4*>(sr + (size_t)row * NSTATES);
    const float4* __restrict__ si4 =
        reinterpret_cast<const float4*>(si + (size_t)row * NSTATES);

    float D0 = 0.f, D1 = 0.f, S = 0.f;
    float A10 = 0.f, A11 = 0.f, A12 = 0.f, A13 = 0.f;

#pragma unroll
    for (int it = 0; it < ITERS; ++it) {
        const int idx = it * THREADS + tid;
        const float4 a = sr4[idx];
        const float4 b = si4[idx];

        const float p0 = a.x * a.x + b.x * b.x;
        const float p1 = a.y * a.y + b.y * b.y;
        const float p2 = a.z * a.z + b.z * b.z;
        const float p3 = a.w * a.w + b.w * b.w;

        const float s01 = p0 + p1;
        const float s23 = p2 + p3;
        const float s   = s01 + s23;

        D0 += (p0 - p1) + (p2 - p3);   // n-bit 0
        D1 += s01 - s23;               // n-bit 1
        S  += s;                       // n-bits 2..9 (per-thread sign below)

        // n-bits 10..13: 'it' is a compile-time constant under full unroll
        A10 += (it & 1) ? -s : s;
        A11 += (it & 2) ? -s : s;
        A12 += (it & 4) ? -s : s;
        A13 += (it & 8) ? -s : s;
    }

    // Expand to the 14 per-qubit partial sums.
    // Qubit q corresponds to n-bit b = 13 - q (qubit 0 is the MSB).
    float v[NQ];
    v[0] = A13;  // b=13
    v[1] = A12;  // b=12
    v[2] = A11;  // b=11
    v[3] = A10;  // b=10
#pragma unroll
    for (int q = 4; q <= 11; ++q) {
        const int b   = 13 - q;               // 9..2
        const int bit = (tid >> (b - 2)) & 1; // n-bit b == tid bit (b-2)
        v[q] = bit ? -S : S;
    }
    v[12] = D1;  // b=1
    v[13] = D0;  // b=0

    // Warp butterfly reduction of all 14 values.
#pragma unroll
    for (int q = 0; q < NQ; ++q) {
#pragma unroll
        for (int off = 16; off > 0; off >>= 1)
            v[q] += __shfl_xor_sync(0xffffffffu, v[q], off);
    }

    __shared__ float red[THREADS / 32][NQ];
    const int warp = tid >> 5;
    const int lane = tid & 31;
    if (lane == 0) {
#pragma unroll
        for (int q = 0; q < NQ; ++q) red[warp][q] = v[q];
    }
    __syncthreads();

    if (tid < NQ) {
        float r = 0.f;
#pragma unroll
        for (int w = 0; w < THREADS / 32; ++w) r += red[w][tid];
        out[(size_t)row * NQ + tid] = r;
    }
}

extern "C" void kernel_launch(void* const* d_in, const int* in_sizes, int n_in,
                              void* d_out, int out_size)
{
    const float* sr = (const float*)d_in[0];  // state_real [4096, 16384]
    const float* si = (const float*)d_in[1];  // state_imag [4096, 16384]
    float* out = (float*)d_out;               // [4096, 14]

    const int batch = in_sizes[0] / NSTATES;  // 4096
    measurement_kernel<<<batch, THREADS>>>(sr, si, out);
}